// round 12
// baseline (speedup 1.0000x reference)
#include <cuda_runtime.h>
#include <cuda_fp16.h>
#include <math.h>
#include <stdint.h>

#define NTOK 32768
#define DDIM 256
#define EEXP 8
#define HDIM 1024
#define MAXENT (NTOK * 2)

// ---------------- static device scratch (no allocations) ----------------
__device__ __half g_xh[(size_t)NTOK * DDIM];
__device__ __half g_hh[(size_t)MAXENT * HDIM];
__device__ float  g_yp[(size_t)MAXENT * DDIM];
__device__ __half g_w1t[(size_t)EEXP * HDIM * DDIM];  // [E][H][D] K-major fp16
__device__ __half g_w2t[(size_t)EEXP * DDIM * HDIM];  // [E][D][H] K-major fp16
__device__ int   g_idx[EEXP * NTOK];
__device__ float g_w  [EEXP * NTOK];
__device__ int   g_cnt[EEXP];

// ---------------- helpers ----------------
__device__ __forceinline__ uint32_t smem_u32(const void* p) {
    uint32_t a;
    asm("{ .reg .u64 t; cvta.to.shared.u64 t, %1; cvt.u32.u64 %0, t; }" : "=r"(a) : "l"(p));
    return a;
}
// SW128: XOR bits[6:4] with bits[9:7]
__device__ __forceinline__ uint32_t swz(uint32_t o) {
    return o ^ ((o >> 3) & 0x70);
}
__device__ __forceinline__ void cpa(uint32_t d, const void* s, int sz) {
    asm volatile("cp.async.cg.shared.global [%0], [%1], 16, %2;" :: "r"(d), "l"(s), "r"(sz));
}
__device__ __forceinline__ void cpa_commit() {
    asm volatile("cp.async.commit_group;" ::: "memory");
}
template<int N>
__device__ __forceinline__ void cpa_wait() {
    asm volatile("cp.async.wait_group %0;" :: "n"(N) : "memory");
}
__device__ __forceinline__ void ldsm4(uint32_t* r, uint32_t a) {
    asm volatile("ldmatrix.sync.aligned.m8n8.x4.shared.b16 {%0,%1,%2,%3}, [%4];"
                 : "=r"(r[0]), "=r"(r[1]), "=r"(r[2]), "=r"(r[3]) : "r"(a));
}
__device__ __forceinline__ void mma16816(float* d, const uint32_t* a, uint32_t b0, uint32_t b1) {
    asm volatile("mma.sync.aligned.m16n8k16.row.col.f32.f16.f16.f32 "
                 "{%0,%1,%2,%3}, {%4,%5,%6,%7}, {%8,%9}, {%0,%1,%2,%3};"
                 : "+f"(d[0]), "+f"(d[1]), "+f"(d[2]), "+f"(d[3])
                 : "r"(a[0]), "r"(a[1]), "r"(a[2]), "r"(a[3]), "r"(b0), "r"(b1));
}
__device__ __forceinline__ float gelu_exact(float v) {
    return 0.5f * v * (1.0f + erff(v * 0.70710678118654752440f));
}

// ---------------- launch 1: W1 transpose+convert (+cnt reset) ----------------
__global__ void prep_w1_kernel(const float* __restrict__ W1) {
    if (blockIdx.x == 0 && blockIdx.y == 0 && blockIdx.z == 0 &&
        threadIdx.y == 0 && threadIdx.x < EEXP) g_cnt[threadIdx.x] = 0;
    __shared__ float t[32][33];
    const int e = blockIdx.z;
    const int c0 = blockIdx.x * 32, r0 = blockIdx.y * 32;
    const int tx = threadIdx.x, ty = threadIdx.y;
    t[ty][tx] = W1[((size_t)e * DDIM + r0 + ty) * HDIM + c0 + tx];
    __syncthreads();
    g_w1t[((size_t)e * HDIM + (c0 + ty)) * DDIM + (r0 + tx)] = __float2half(t[tx][ty]);
}

// ---------------- launch 2: W2 transpose+convert ----------------
__global__ void prep_w2_kernel(const float* __restrict__ W2) {
    __shared__ float t[32][33];
    const int e = blockIdx.z;
    const int c0 = blockIdx.y * 32, r0 = blockIdx.x * 32;
    const int tx = threadIdx.x, ty = threadIdx.y;
    t[ty][tx] = W2[((size_t)e * HDIM + r0 + ty) * DDIM + c0 + tx];
    __syncthreads();
    g_w2t[((size_t)e * DDIM + (c0 + ty)) * HDIM + (r0 + tx)] = __float2half(t[tx][ty]);
}

// ---------------- launch 3: router + x->fp16 (warp per token) ----------------
__global__ void router_kernel(const float* __restrict__ x,
                              const float* __restrict__ grad,
                              const float* __restrict__ Wr,
                              const float* __restrict__ br,
                              float* __restrict__ probs_out) {
    __shared__ float sWrT[EEXP][DDIM];
    __shared__ float sWg[EEXP];
    __shared__ float sbr[EEXP];
    const int tid = threadIdx.x;
    for (int i = tid; i < DDIM * EEXP; i += blockDim.x) {
        const int d = i >> 3, e = i & 7;
        sWrT[e][d] = Wr[d * EEXP + e];
    }
    if (tid < EEXP) { sWg[tid] = Wr[DDIM * EEXP + tid]; sbr[tid] = br[tid]; }
    __syncthreads();

    const int warp = tid >> 5, lane = tid & 31;
    const int n = blockIdx.x * 8 + warp;

    float acc[EEXP];
#pragma unroll
    for (int e = 0; e < EEXP; e++) acc[e] = 0.f;

    const float* xr = x + (size_t)n * DDIM;
    __half* xh = g_xh + (size_t)n * DDIM;
#pragma unroll
    for (int it = 0; it < DDIM / 32; it++) {
        const int d = it * 32 + lane;
        const float xv = xr[d];
        xh[d] = __float2half(xv);
#pragma unroll
        for (int e = 0; e < EEXP; e++) acc[e] += xv * sWrT[e][d];
    }
#pragma unroll
    for (int e = 0; e < EEXP; e++) {
        float v = acc[e];
#pragma unroll
        for (int o = 16; o > 0; o >>= 1) v += __shfl_xor_sync(0xffffffffu, v, o);
        acc[e] = v;
    }
    if (lane == 0) {
        const float g = grad[n];
        float mx = -1e30f;
#pragma unroll
        for (int e = 0; e < EEXP; e++) {
            acc[e] += g * sWg[e] + sbr[e];
            mx = fmaxf(mx, acc[e]);
        }
        float s = 0.f;
#pragma unroll
        for (int e = 0; e < EEXP; e++) { acc[e] = expf(acc[e] - mx); s += acc[e]; }
        const float inv = 1.f / s;
#pragma unroll
        for (int e = 0; e < EEXP; e++) {
            acc[e] *= inv;
            probs_out[(size_t)n * EEXP + e] = acc[e];
        }
        int e0 = 0;
#pragma unroll
        for (int e = 1; e < EEXP; e++) if (acc[e] > acc[e0]) e0 = e;
        int e1 = (e0 == 0) ? 1 : 0;
#pragma unroll
        for (int e = 0; e < EEXP; e++) if (e != e0 && acc[e] > acc[e1]) e1 = e;

        int p0 = atomicAdd(&g_cnt[e0], 1);
        g_idx[e0 * NTOK + p0] = (n << 1);
        g_w  [e0 * NTOK + p0] = acc[e0];
        int p1 = atomicAdd(&g_cnt[e1], 1);
        g_idx[e1 * NTOK + p1] = (n << 1) | 1;
        g_w  [e1 * NTOK + p1] = acc[e1];
    }
}

// ---------------- launches 4/5: HMMA GEMM, CTA 128x256, 512 thr, warp 32x64, K-chunk 64 ----
// 3-stage ring, 1 sync/chunk. Stage (48KB): A[128][64] @0 (16K) | B[256][64] @16K (32K).
// G1=true : A = gathered x (K=256), B = W1T, epilogue gelu -> g_hh
// G1=false: A = g_hh (K=1024), B = W2T, epilogue w*(acc+b2) float2-store -> g_yp
template<int KDIM, bool G1>
__global__ __launch_bounds__(512, 1)
void moe_gemm_kernel(const float* __restrict__ bias) {
    constexpr int NC = KDIM / 64;
    constexpr int BROWS = G1 ? HDIM : DDIM;
    constexpr uint32_t STAGE = 49152;

    const int e = blockIdx.z;
    int off = 0;
#pragma unroll
    for (int i = 0; i < EEXP; i++) if (i < e) off += g_cnt[i];
    const int cnt = g_cnt[e];
    const int m0 = blockIdx.y * 128;
    if (m0 >= cnt) return;
    const int n0 = blockIdx.x * 256;
    const int mRem = min(cnt - m0, 128);

    extern __shared__ char smem[];
    const uint32_t sb = smem_u32(smem);
    __shared__ float sBias[256];

    const int tid = threadIdx.x, lane = tid & 31, wid = tid >> 5;
    const int warpM = wid & 3, warpN = wid >> 2;   // 4x4 warps, warp tile 32x64

    if (tid < 256) sBias[tid] = bias[e * BROWS + n0 + tid];

    // ---- loader: A row = tid>>2 (128 rows), quarter = tid&3 (32B = 2x16B) ----
    const int alr = tid >> 2, alq = tid & 3;
    const bool aval = alr < mRem;
    const __half* arow;
    {
        int row;
        if (G1) row = aval ? (g_idx[e * NTOK + m0 + alr] >> 1) : 0;
        else    row = aval ? (off + m0 + alr) : 0;
        arow = (G1 ? g_xh : g_hh) + (size_t)row * KDIM;
    }
    const int asz = aval ? 16 : 0;
    // ---- loader: B row = tid>>1 (256 rows), half = tid&1 (64B = 4x16B) ----
    const int blr = tid >> 1, blh = tid & 1;
    const __half* bt = (G1 ? g_w1t : g_w2t) + ((size_t)e * BROWS + n0 + blr) * KDIM;

    uint32_t stA[2], stB[4];
#pragma unroll
    for (int j = 0; j < 2; j++) stA[j] = swz((uint32_t)alr * 128 + alq * 32 + j * 16);
#pragma unroll
    for (int j = 0; j < 4; j++) stB[j] = 16384u + swz((uint32_t)blr * 128 + blh * 64 + j * 16);

    // ldmatrix UNSWIZZLED base offsets; swizzle applied at use: swz(base + ks*32)
    uint32_t aoff[2], boff[4];
#pragma unroll
    for (int mt = 0; mt < 2; mt++) {
        const uint32_t row = warpM * 32 + mt * 16 + (lane & 15);
        aoff[mt] = row * 128 + (lane >> 4) * 16;
    }
#pragma unroll
    for (int btj = 0; btj < 4; btj++) {
        const uint32_t row = warpN * 64 + btj * 16 + (lane & 7) + ((lane >> 4) & 1) * 8;
        boff[btj] = row * 128 + ((lane >> 3) & 1) * 16;
    }

    float acc[2][8][4];
#pragma unroll
    for (int i = 0; i < 2; i++)
#pragma unroll
        for (int j = 0; j < 8; j++)
#pragma unroll
            for (int q = 0; q < 4; q++) acc[i][j][q] = 0.f;

    auto load_chunk = [&](int kc, int stage) {
        const uint32_t s = sb + (uint32_t)stage * STAGE;
        const int ga = kc * 64 + alq * 16;
#pragma unroll
        for (int j = 0; j < 2; j++) cpa(s + stA[j], arow + ga + j * 8, asz);
        const int gb = kc * 64 + blh * 32;
#pragma unroll
        for (int j = 0; j < 4; j++) cpa(s + stB[j], bt + gb + j * 8, 16);
    };

    load_chunk(0, 0);
    cpa_commit();
    if (NC > 1) { load_chunk(1, 1); cpa_commit(); }

    int stage = 0;
    for (int c = 0; c < NC; c++) {
        if (c + 1 < NC) cpa_wait<1>(); else cpa_wait<0>();
        __syncthreads();
        if (c + 2 < NC) {
            int ps = stage + 2; if (ps >= 3) ps -= 3;
            load_chunk(c + 2, ps);
            cpa_commit();
        }

        const uint32_t ss = sb + (uint32_t)stage * STAGE;
#pragma unroll
        for (int ks = 0; ks < 4; ks++) {
            uint32_t ah[2][4], bb[4][4];
            ldsm4(ah[0], ss + swz(aoff[0] + ks * 32));
            ldsm4(ah[1], ss + swz(aoff[1] + ks * 32));
#pragma unroll
            for (int btj = 0; btj < 4; btj++)
                ldsm4(bb[btj], ss + 16384u + swz(boff[btj] + ks * 32));
#pragma unroll
            for (int mt = 0; mt < 2; mt++)
#pragma unroll
                for (int btj = 0; btj < 4; btj++) {
                    mma16816(acc[mt][2 * btj],     ah[mt], bb[btj][0], bb[btj][1]);
                    mma16816(acc[mt][2 * btj + 1], ah[mt], bb[btj][2], bb[btj][3]);
                }
        }
        if (++stage == 3) stage = 0;
    }

    // ---------------- epilogue ----------------
    const int gid = lane >> 2, tig = lane & 3;
#pragma unroll
    for (int mt = 0; mt < 2; mt++) {
#pragma unroll
        for (int half = 0; half < 2; half++) {
            const int ml = warpM * 32 + mt * 16 + gid + half * 8;
            if (ml >= mRem) continue;
            if (G1) {
                const size_t ob = (size_t)(off + m0 + ml) * HDIM + n0;
#pragma unroll
                for (int nt = 0; nt < 8; nt++) {
                    const int col = warpN * 64 + nt * 8 + tig * 2;
                    const float v0 = gelu_exact(acc[mt][nt][half * 2]     + sBias[col]);
                    const float v1 = gelu_exact(acc[mt][nt][half * 2 + 1] + sBias[col + 1]);
                    __half2 hp; hp.x = __float2half(v0); hp.y = __float2half(v1);
                    *(uint32_t*)(g_hh + ob + col) = *(uint32_t*)&hp;
                }
            } else {
                const int ent = g_idx[e * NTOK + m0 + ml];
                const float wgt = g_w[e * NTOK + m0 + ml];
                float* dst = g_yp + (size_t)ent * DDIM + n0;
#pragma unroll
                for (int nt = 0; nt < 8; nt++) {
                    const int col = warpN * 64 + nt * 8 + tig * 2;
                    float2 v;
                    v.x = wgt * (acc[mt][nt][half * 2]     + sBias[col]);
                    v.y = wgt * (acc[mt][nt][half * 2 + 1] + sBias[col + 1]);
                    *(float2*)(dst + col) = v;
                }
            }
        }
    }
}

// ---------------- launch 6: combine the two weighted slots per token ----------------
__global__ void combine_kernel(float* __restrict__ out) {
    const int i = blockIdx.x * blockDim.x + threadIdx.x;
    const int n  = i / (DDIM / 4);
    const int d4 = i % (DDIM / 4);
    const float4* yp4 = (const float4*)g_yp;
    const float4 u = yp4[(size_t)n * (2 * DDIM / 4) + d4];
    const float4 v = yp4[(size_t)n * (2 * DDIM / 4) + (DDIM / 4) + d4];
    float4 r;
    r.x = u.x + v.x; r.y = u.y + v.y; r.z = u.z + v.z; r.w = u.w + v.w;
    ((float4*)out)[i] = r;
}

// ---------------- launch ----------------
extern "C" void kernel_launch(void* const* d_in, const int* in_sizes, int n_in,
                              void* d_out, int out_size) {
    const float* x    = (const float*)d_in[0];
    const float* grad = (const float*)d_in[1];
    const float* Wr   = (const float*)d_in[2];
    const float* br   = (const float*)d_in[3];
    const float* W1   = (const float*)d_in[4];
    const float* b1   = (const float*)d_in[5];
    const float* W2   = (const float*)d_in[6];
    const float* b2   = (const float*)d_in[7];
    float* out   = (float*)d_out;
    float* probs = out + (size_t)NTOK * DDIM;

    const int SMEM_DYN = 3 * 49152;
    cudaFuncSetAttribute(moe_gemm_kernel<DDIM, true>,  cudaFuncAttributeMaxDynamicSharedMemorySize, SMEM_DYN);
    cudaFuncSetAttribute(moe_gemm_kernel<HDIM, false>, cudaFuncAttributeMaxDynamicSharedMemorySize, SMEM_DYN);

    prep_w1_kernel<<<dim3(HDIM / 32, DDIM / 32, EEXP), dim3(32, 32)>>>(W1);       // 1 (+cnt reset)
    prep_w2_kernel<<<dim3(HDIM / 32, DDIM / 32, EEXP), dim3(32, 32)>>>(W2);       // 2
    router_kernel<<<NTOK / 8, 256>>>(x, grad, Wr, br, probs);                     // 3
    moe_gemm_kernel<DDIM, true><<<dim3(HDIM / 256, NTOK / 128, EEXP), 512, SMEM_DYN>>>(b1);  // 4 (profiled)
    moe_gemm_kernel<HDIM, false><<<dim3(DDIM / 256, NTOK / 128, EEXP), 512, SMEM_DYN>>>(b2); // 5
    combine_kernel<<<(NTOK * DDIM / 4) / 256, 256>>>(out);                        // 6
}

// round 13
// speedup vs baseline: 1.0657x; 1.0657x over previous
#include <cuda_runtime.h>
#include <cuda_fp16.h>
#include <math.h>
#include <stdint.h>

#define NTOK 32768
#define DDIM 256
#define EEXP 8
#define HDIM 1024
#define MAXENT (NTOK * 2)

// ---------------- static device scratch (no allocations) ----------------
__device__ __half g_xh[(size_t)NTOK * DDIM];
__device__ __half g_hh[(size_t)MAXENT * HDIM];
__device__ float  g_yp[(size_t)MAXENT * DDIM];
__device__ __half g_w1t[(size_t)EEXP * HDIM * DDIM];  // [E][H][D] K-major fp16
__device__ __half g_w2t[(size_t)EEXP * DDIM * HDIM];  // [E][D][H] K-major fp16
__device__ int   g_idx[EEXP * NTOK];
__device__ float g_w  [EEXP * NTOK];
__device__ int   g_cnt[EEXP];

// ---------------- helpers ----------------
__device__ __forceinline__ uint32_t smem_u32(const void* p) {
    uint32_t a;
    asm("{ .reg .u64 t; cvta.to.shared.u64 t, %1; cvt.u32.u64 %0, t; }" : "=r"(a) : "l"(p));
    return a;
}
// SW128: XOR bits[6:4] with bits[9:7]
__device__ __forceinline__ uint32_t swz(uint32_t o) {
    return o ^ ((o >> 3) & 0x70);
}
__device__ __forceinline__ void cpa(uint32_t d, const void* s, int sz) {
    asm volatile("cp.async.cg.shared.global [%0], [%1], 16, %2;" :: "r"(d), "l"(s), "r"(sz));
}
__device__ __forceinline__ void cpa_commit() {
    asm volatile("cp.async.commit_group;" ::: "memory");
}
template<int N>
__device__ __forceinline__ void cpa_wait() {
    asm volatile("cp.async.wait_group %0;" :: "n"(N) : "memory");
}
__device__ __forceinline__ void ldsm4(uint32_t* r, uint32_t a) {
    asm volatile("ldmatrix.sync.aligned.m8n8.x4.shared.b16 {%0,%1,%2,%3}, [%4];"
                 : "=r"(r[0]), "=r"(r[1]), "=r"(r[2]), "=r"(r[3]) : "r"(a));
}
__device__ __forceinline__ void mma16816(float* d, const uint32_t* a, uint32_t b0, uint32_t b1) {
    asm volatile("mma.sync.aligned.m16n8k16.row.col.f32.f16.f16.f32 "
                 "{%0,%1,%2,%3}, {%4,%5,%6,%7}, {%8,%9}, {%0,%1,%2,%3};"
                 : "+f"(d[0]), "+f"(d[1]), "+f"(d[2]), "+f"(d[3])
                 : "r"(a[0]), "r"(a[1]), "r"(a[2]), "r"(a[3]), "r"(b0), "r"(b1));
}
// exact gelu for the router-free paths (not perf-critical)
__device__ __forceinline__ float gelu_exact(float v) {
    return 0.5f * v * (1.0f + erff(v * 0.70710678118654752440f));
}
// Branchless gelu via Abramowitz-Stegun 7.1.26 (max abs erf err 1.5e-7, far
// below the fp16 storage truncation of h). 2 MUFU (rcp, ex2), no divergence.
__device__ __forceinline__ float gelu_fast(float v) {
    const float t = fabsf(v) * 0.70710678118654752440f;
    const float k = __fdividef(1.0f, fmaf(0.3275911f, t, 1.0f));
    float p = fmaf(1.061405429f, k, -1.453152027f);
    p = fmaf(p, k, 1.421413741f);
    p = fmaf(p, k, -0.284496736f);
    p = fmaf(p, k, 0.254829592f);
    p *= k;
    const float er = 1.0f - p * __expf(-t * t);
    return 0.5f * v * fmaf(copysignf(er, v), 1.0f, 1.0f);
}

// ---------------- launch 1: W1 transpose+convert (+cnt reset) ----------------
__global__ void prep_w1_kernel(const float* __restrict__ W1) {
    if (blockIdx.x == 0 && blockIdx.y == 0 && blockIdx.z == 0 &&
        threadIdx.y == 0 && threadIdx.x < EEXP) g_cnt[threadIdx.x] = 0;
    __shared__ float t[32][33];
    const int e = blockIdx.z;
    const int c0 = blockIdx.x * 32, r0 = blockIdx.y * 32;
    const int tx = threadIdx.x, ty = threadIdx.y;
    t[ty][tx] = W1[((size_t)e * DDIM + r0 + ty) * HDIM + c0 + tx];
    __syncthreads();
    g_w1t[((size_t)e * HDIM + (c0 + ty)) * DDIM + (r0 + tx)] = __float2half(t[tx][ty]);
}

// ---------------- launch 2: W2 transpose+convert ----------------
__global__ void prep_w2_kernel(const float* __restrict__ W2) {
    __shared__ float t[32][33];
    const int e = blockIdx.z;
    const int c0 = blockIdx.y * 32, r0 = blockIdx.x * 32;
    const int tx = threadIdx.x, ty = threadIdx.y;
    t[ty][tx] = W2[((size_t)e * HDIM + r0 + ty) * DDIM + c0 + tx];
    __syncthreads();
    g_w2t[((size_t)e * DDIM + (c0 + ty)) * HDIM + (r0 + tx)] = __float2half(t[tx][ty]);
}

// ---------------- launch 3: router + x->fp16 (warp per token) ----------------
__global__ void router_kernel(const float* __restrict__ x,
                              const float* __restrict__ grad,
                              const float* __restrict__ Wr,
                              const float* __restrict__ br,
                              float* __restrict__ probs_out) {
    __shared__ float sWrT[EEXP][DDIM];
    __shared__ float sWg[EEXP];
    __shared__ float sbr[EEXP];
    const int tid = threadIdx.x;
    for (int i = tid; i < DDIM * EEXP; i += blockDim.x) {
        const int d = i >> 3, e = i & 7;
        sWrT[e][d] = Wr[d * EEXP + e];
    }
    if (tid < EEXP) { sWg[tid] = Wr[DDIM * EEXP + tid]; sbr[tid] = br[tid]; }
    __syncthreads();

    const int warp = tid >> 5, lane = tid & 31;
    const int n = blockIdx.x * 8 + warp;

    float acc[EEXP];
#pragma unroll
    for (int e = 0; e < EEXP; e++) acc[e] = 0.f;

    const float* xr = x + (size_t)n * DDIM;
    __half* xh = g_xh + (size_t)n * DDIM;
#pragma unroll
    for (int it = 0; it < DDIM / 32; it++) {
        const int d = it * 32 + lane;
        const float xv = xr[d];
        xh[d] = __float2half(xv);
#pragma unroll
        for (int e = 0; e < EEXP; e++) acc[e] += xv * sWrT[e][d];
    }
#pragma unroll
    for (int e = 0; e < EEXP; e++) {
        float v = acc[e];
#pragma unroll
        for (int o = 16; o > 0; o >>= 1) v += __shfl_xor_sync(0xffffffffu, v, o);
        acc[e] = v;
    }
    if (lane == 0) {
        const float g = grad[n];
        float mx = -1e30f;
#pragma unroll
        for (int e = 0; e < EEXP; e++) {
            acc[e] += g * sWg[e] + sbr[e];
            mx = fmaxf(mx, acc[e]);
        }
        float s = 0.f;
#pragma unroll
        for (int e = 0; e < EEXP; e++) { acc[e] = expf(acc[e] - mx); s += acc[e]; }
        const float inv = 1.f / s;
#pragma unroll
        for (int e = 0; e < EEXP; e++) {
            acc[e] *= inv;
            probs_out[(size_t)n * EEXP + e] = acc[e];
        }
        int e0 = 0;
#pragma unroll
        for (int e = 1; e < EEXP; e++) if (acc[e] > acc[e0]) e0 = e;
        int e1 = (e0 == 0) ? 1 : 0;
#pragma unroll
        for (int e = 0; e < EEXP; e++) if (e != e0 && acc[e] > acc[e1]) e1 = e;

        int p0 = atomicAdd(&g_cnt[e0], 1);
        g_idx[e0 * NTOK + p0] = (n << 1);
        g_w  [e0 * NTOK + p0] = acc[e0];
        int p1 = atomicAdd(&g_cnt[e1], 1);
        g_idx[e1 * NTOK + p1] = (n << 1) | 1;
        g_w  [e1 * NTOK + p1] = acc[e1];
    }
}

// ---------------- launches 4/5: HMMA GEMM, 128x128 tile, K-chunk 64, 3-stage, 1 sync/chunk ----
// Stage (32KB): A[128][64] @0 | B[128][64] @16K  (fp16, 128B rows, SW128)
// G1=true : A = gathered x (K=256), B = W1T, epilogue gelu_fast -> g_hh
// G1=false: A = g_hh (K=1024), B = W2T, epilogue w*(acc+b2) float2-store -> g_yp
template<int KDIM, bool G1>
__global__ __launch_bounds__(256, 2)
void moe_gemm_kernel(const float* __restrict__ bias) {
    constexpr int NC = KDIM / 64;
    constexpr int BROWS = G1 ? HDIM : DDIM;
    constexpr uint32_t STAGE = 32768;

    const int e = blockIdx.z;
    int off = 0;
#pragma unroll
    for (int i = 0; i < EEXP; i++) if (i < e) off += g_cnt[i];
    const int cnt = g_cnt[e];
    const int m0 = blockIdx.y * 128;
    if (m0 >= cnt) return;
    const int n0 = blockIdx.x * 128;
    const int mRem = min(cnt - m0, 128);

    extern __shared__ char smem[];
    const uint32_t sb = smem_u32(smem);
    __shared__ float sBias[128];

    const int tid = threadIdx.x, lane = tid & 31, wid = tid >> 5;
    const int warpM = wid & 3, warpN = wid >> 2;   // 4x2 warps, warp tile 32x64

    if (tid < 128) sBias[tid] = bias[e * BROWS + n0 + tid];

    // loader: row lr = tid>>1, half lh = tid&1 (64B each, 4x16B)
    const int lr = tid >> 1, lh = tid & 1;
    const bool aval = lr < mRem;
    const __half* arow;
    {
        int row;
        if (G1) row = aval ? (g_idx[e * NTOK + m0 + lr] >> 1) : 0;
        else    row = aval ? (off + m0 + lr) : 0;
        arow = (G1 ? g_xh : g_hh) + (size_t)row * KDIM;
    }
    const __half* bt = (G1 ? g_w1t : g_w2t) + ((size_t)e * BROWS + n0 + lr) * KDIM;
    const int asz = aval ? 16 : 0;

    uint32_t stW[4];
#pragma unroll
    for (int j = 0; j < 4; j++) stW[j] = swz((uint32_t)lr * 128 + lh * 64 + j * 16);

    // ldmatrix UNSWIZZLED base offsets; swizzle applied at use: swz(base + ks*32)
    uint32_t aoff[2], boff[4];
#pragma unroll
    for (int mt = 0; mt < 2; mt++) {
        const uint32_t row = warpM * 32 + mt * 16 + (lane & 15);
        aoff[mt] = row * 128 + (lane >> 4) * 16;
    }
#pragma unroll
    for (int btj = 0; btj < 4; btj++) {
        const uint32_t row = warpN * 64 + btj * 16 + (lane & 7) + ((lane >> 4) & 1) * 8;
        boff[btj] = row * 128 + ((lane >> 3) & 1) * 16;
    }

    float acc[2][8][4];
#pragma unroll
    for (int i = 0; i < 2; i++)
#pragma unroll
        for (int j = 0; j < 8; j++)
#pragma unroll
            for (int q = 0; q < 4; q++) acc[i][j][q] = 0.f;

    auto load_chunk = [&](int kc, int stage) {
        const uint32_t s = sb + (uint32_t)stage * STAGE;
        const int go = kc * 64 + lh * 32;   // halves
#pragma unroll
        for (int j = 0; j < 4; j++) {
            cpa(s + stW[j],          arow + go + j * 8, asz);
            cpa(s + 16384u + stW[j], bt   + go + j * 8, 16);
        }
    };

    load_chunk(0, 0);
    cpa_commit();
    if (NC > 1) { load_chunk(1, 1); cpa_commit(); }

    int stage = 0;
    for (int c = 0; c < NC; c++) {
        if (c + 1 < NC) cpa_wait<1>(); else cpa_wait<0>();
        __syncthreads();
        if (c + 2 < NC) {
            int ps = stage + 2; if (ps >= 3) ps -= 3;
            load_chunk(c + 2, ps);
            cpa_commit();
        }

        const uint32_t ss = sb + (uint32_t)stage * STAGE;
#pragma unroll
        for (int ks = 0; ks < 4; ks++) {
            uint32_t ah[2][4], bb[4][4];
            ldsm4(ah[0], ss + swz(aoff[0] + ks * 32));
            ldsm4(ah[1], ss + swz(aoff[1] + ks * 32));
#pragma unroll
            for (int btj = 0; btj < 4; btj++)
                ldsm4(bb[btj], ss + 16384u + swz(boff[btj] + ks * 32));
#pragma unroll
            for (int mt = 0; mt < 2; mt++)
#pragma unroll
                for (int btj = 0; btj < 4; btj++) {
                    mma16816(acc[mt][2 * btj],     ah[mt], bb[btj][0], bb[btj][1]);
                    mma16816(acc[mt][2 * btj + 1], ah[mt], bb[btj][2], bb[btj][3]);
                }
        }
        if (++stage == 3) stage = 0;
    }

    // ---------------- epilogue ----------------
    const int gid = lane >> 2, tig = lane & 3;
#pragma unroll
    for (int mt = 0; mt < 2; mt++) {
#pragma unroll
        for (int half = 0; half < 2; half++) {
            const int ml = warpM * 32 + mt * 16 + gid + half * 8;
            if (ml >= mRem) continue;
            if (G1) {
                __half* hbase = g_hh + (size_t)(off + m0 + ml) * HDIM + n0 + warpN * 64 + tig * 2;
#pragma unroll
                for (int nt = 0; nt < 8; nt++) {
                    const int col = warpN * 64 + nt * 8 + tig * 2;
                    const float v0 = gelu_fast(acc[mt][nt][half * 2]     + sBias[col]);
                    const float v1 = gelu_fast(acc[mt][nt][half * 2 + 1] + sBias[col + 1]);
                    const __half2 hp = __floats2half2_rn(v0, v1);
                    *(__half2*)(hbase + nt * 8) = hp;
                }
            } else {
                const int ent = g_idx[e * NTOK + m0 + ml];
                const float wgt = g_w[e * NTOK + m0 + ml];
                float* dst = g_yp + (size_t)ent * DDIM + n0 + warpN * 64 + tig * 2;
#pragma unroll
                for (int nt = 0; nt < 8; nt++) {
                    const int col = warpN * 64 + nt * 8 + tig * 2;
                    float2 v;
                    v.x = wgt * (acc[mt][nt][half * 2]     + sBias[col]);
                    v.y = wgt * (acc[mt][nt][half * 2 + 1] + sBias[col + 1]);
                    *(float2*)(dst + nt * 8) = v;
                }
            }
        }
    }
}

// ---------------- launch 6: combine the two weighted slots per token ----------------
__global__ void combine_kernel(float* __restrict__ out) {
    const int i = blockIdx.x * blockDim.x + threadIdx.x;
    const int n  = i / (DDIM / 4);
    const int d4 = i % (DDIM / 4);
    const float4* yp4 = (const float4*)g_yp;
    const float4 u = yp4[(size_t)n * (2 * DDIM / 4) + d4];
    const float4 v = yp4[(size_t)n * (2 * DDIM / 4) + (DDIM / 4) + d4];
    float4 r;
    r.x = u.x + v.x; r.y = u.y + v.y; r.z = u.z + v.z; r.w = u.w + v.w;
    ((float4*)out)[i] = r;
}

// ---------------- launch ----------------
extern "C" void kernel_launch(void* const* d_in, const int* in_sizes, int n_in,
                              void* d_out, int out_size) {
    const float* x    = (const float*)d_in[0];
    const float* grad = (const float*)d_in[1];
    const float* Wr   = (const float*)d_in[2];
    const float* br   = (const float*)d_in[3];
    const float* W1   = (const float*)d_in[4];
    const float* b1   = (const float*)d_in[5];
    const float* W2   = (const float*)d_in[6];
    const float* b2   = (const float*)d_in[7];
    float* out   = (float*)d_out;
    float* probs = out + (size_t)NTOK * DDIM;

    const int SMEM_DYN = 3 * 32768;
    cudaFuncSetAttribute(moe_gemm_kernel<DDIM, true>,  cudaFuncAttributeMaxDynamicSharedMemorySize, SMEM_DYN);
    cudaFuncSetAttribute(moe_gemm_kernel<HDIM, false>, cudaFuncAttributeMaxDynamicSharedMemorySize, SMEM_DYN);

    prep_w1_kernel<<<dim3(HDIM / 32, DDIM / 32, EEXP), dim3(32, 32)>>>(W1);       // 1 (+cnt reset)
    prep_w2_kernel<<<dim3(HDIM / 32, DDIM / 32, EEXP), dim3(32, 32)>>>(W2);       // 2
    router_kernel<<<NTOK / 8, 256>>>(x, grad, Wr, br, probs);                     // 3
    moe_gemm_kernel<DDIM, true><<<dim3(HDIM / 128, NTOK / 128, EEXP), 256, SMEM_DYN>>>(b1);  // 4 (profiled)
    moe_gemm_kernel<HDIM, false><<<dim3(DDIM / 128, NTOK / 128, EEXP), 256, SMEM_DYN>>>(b2); // 5
    combine_kernel<<<(NTOK * DDIM / 4) / 256, 256>>>(out);                        // 6
}

// round 14
// speedup vs baseline: 1.0765x; 1.0101x over previous
#include <cuda_runtime.h>
#include <cuda_fp16.h>
#include <math.h>
#include <stdint.h>

#define NTOK 32768
#define DDIM 256
#define EEXP 8
#define HDIM 1024
#define MAXENT (NTOK * 2)

// ---------------- static device scratch (no allocations) ----------------
__device__ __half g_xh[(size_t)NTOK * DDIM];
__device__ __half g_hh[(size_t)MAXENT * HDIM];
__device__ __half g_yp[(size_t)MAXENT * DDIM];        // fp16 weighted expert outputs
__device__ __half g_w1t[(size_t)EEXP * HDIM * DDIM];  // [E][H][D] K-major fp16
__device__ __half g_w2t[(size_t)EEXP * DDIM * HDIM];  // [E][D][H] K-major fp16
__device__ int   g_idx[EEXP * NTOK];
__device__ float g_w  [EEXP * NTOK];
__device__ int   g_cnt[EEXP];

// ---------------- helpers ----------------
__device__ __forceinline__ uint32_t smem_u32(const void* p) {
    uint32_t a;
    asm("{ .reg .u64 t; cvta.to.shared.u64 t, %1; cvt.u32.u64 %0, t; }" : "=r"(a) : "l"(p));
    return a;
}
// SW128: XOR bits[6:4] with bits[9:7]
__device__ __forceinline__ uint32_t swz(uint32_t o) {
    return o ^ ((o >> 3) & 0x70);
}
__device__ __forceinline__ void cpa(uint32_t d, const void* s, int sz) {
    asm volatile("cp.async.cg.shared.global [%0], [%1], 16, %2;" :: "r"(d), "l"(s), "r"(sz));
}
__device__ __forceinline__ void cpa_commit() {
    asm volatile("cp.async.commit_group;" ::: "memory");
}
template<int N>
__device__ __forceinline__ void cpa_wait() {
    asm volatile("cp.async.wait_group %0;" :: "n"(N) : "memory");
}
__device__ __forceinline__ void ldsm4(uint32_t* r, uint32_t a) {
    asm volatile("ldmatrix.sync.aligned.m8n8.x4.shared.b16 {%0,%1,%2,%3}, [%4];"
                 : "=r"(r[0]), "=r"(r[1]), "=r"(r[2]), "=r"(r[3]) : "r"(a));
}
__device__ __forceinline__ void mma16816(float* d, const uint32_t* a, uint32_t b0, uint32_t b1) {
    asm volatile("mma.sync.aligned.m16n8k16.row.col.f32.f16.f16.f32 "
                 "{%0,%1,%2,%3}, {%4,%5,%6,%7}, {%8,%9}, {%0,%1,%2,%3};"
                 : "+f"(d[0]), "+f"(d[1]), "+f"(d[2]), "+f"(d[3])
                 : "r"(a[0]), "r"(a[1]), "r"(a[2]), "r"(a[3]), "r"(b0), "r"(b1));
}
// Branchless gelu via Abramowitz-Stegun 7.1.26 (max abs erf err 1.5e-7).
__device__ __forceinline__ float gelu_fast(float v) {
    const float t = fabsf(v) * 0.70710678118654752440f;
    const float k = __fdividef(1.0f, fmaf(0.3275911f, t, 1.0f));
    float p = fmaf(1.061405429f, k, -1.453152027f);
    p = fmaf(p, k, 1.421413741f);
    p = fmaf(p, k, -0.284496736f);
    p = fmaf(p, k, 0.254829592f);
    p *= k;
    const float er = 1.0f - p * __expf(-t * t);
    return 0.5f * v * fmaf(copysignf(er, v), 1.0f, 1.0f);
}

// ---------------- launch 1: W1+W2 transpose+convert (+cnt reset) ----------------
// grid (32, 8, 16): z<8 -> W1[e=z]; z>=8 -> W2[e=z-8]
__global__ void prep_w_kernel(const float* __restrict__ W1, const float* __restrict__ W2) {
    if (blockIdx.x == 0 && blockIdx.y == 0 && blockIdx.z == 0 &&
        threadIdx.y == 0 && threadIdx.x < EEXP) g_cnt[threadIdx.x] = 0;
    __shared__ float t[32][33];
    const int z = blockIdx.z;
    const bool isW1 = z < EEXP;
    const int e = isW1 ? z : z - EEXP;
    const int R = isW1 ? DDIM : HDIM;
    const int C = isW1 ? HDIM : DDIM;
    const int c0 = (isW1 ? blockIdx.x : blockIdx.y) * 32;
    const int r0 = (isW1 ? blockIdx.y : blockIdx.x) * 32;
    const float* W = isW1 ? W1 : W2;
    const int tx = threadIdx.x, ty = threadIdx.y;
    t[ty][tx] = W[((size_t)e * R + r0 + ty) * C + c0 + tx];
    __syncthreads();
    const float v = t[tx][ty];
    const size_t oi = ((size_t)e * C + (c0 + ty)) * R + (r0 + tx);
    if (isW1) g_w1t[oi] = __float2half(v);
    else      g_w2t[oi] = __float2half(v);
}

// ---------------- launch 2: router + x->fp16 (warp per token, float4 path) ----------------
__global__ void router_kernel(const float* __restrict__ x,
                              const float* __restrict__ grad,
                              const float* __restrict__ Wr,
                              const float* __restrict__ br,
                              float* __restrict__ probs_out) {
    __shared__ float sWrT[EEXP][DDIM];
    __shared__ float sWg[EEXP];
    __shared__ float sbr[EEXP];
    const int tid = threadIdx.x;
    for (int i = tid; i < DDIM * EEXP; i += blockDim.x) {
        const int d = i >> 3, e = i & 7;
        sWrT[e][d] = Wr[d * EEXP + e];
    }
    if (tid < EEXP) { sWg[tid] = Wr[DDIM * EEXP + tid]; sbr[tid] = br[tid]; }
    __syncthreads();

    const int warp = tid >> 5, lane = tid & 31;
    const int n = blockIdx.x * 8 + warp;

    float acc[EEXP];
#pragma unroll
    for (int e = 0; e < EEXP; e++) acc[e] = 0.f;

    const float4* xr4 = (const float4*)(x + (size_t)n * DDIM);
    uint2* xh2 = (uint2*)(g_xh + (size_t)n * DDIM);
#pragma unroll
    for (int r = 0; r < 2; r++) {
        const int q = r * 32 + lane;         // float4 index; d = q*4
        const float4 v = xr4[q];
        const __half2 h01 = __floats2half2_rn(v.x, v.y);
        const __half2 h23 = __floats2half2_rn(v.z, v.w);
        uint2 pk;
        pk.x = *(const uint32_t*)&h01;
        pk.y = *(const uint32_t*)&h23;
        xh2[q] = pk;
        const int d = q * 4;
#pragma unroll
        for (int e = 0; e < EEXP; e++) {
            const float4 w = *(const float4*)&sWrT[e][d];
            acc[e] = fmaf(v.x, w.x, fmaf(v.y, w.y, fmaf(v.z, w.z, fmaf(v.w, w.w, acc[e]))));
        }
    }
#pragma unroll
    for (int e = 0; e < EEXP; e++) {
        float v = acc[e];
#pragma unroll
        for (int o = 16; o > 0; o >>= 1) v += __shfl_xor_sync(0xffffffffu, v, o);
        acc[e] = v;
    }
    if (lane == 0) {
        const float g = grad[n];
        float mx = -1e30f;
#pragma unroll
        for (int e = 0; e < EEXP; e++) {
            acc[e] += g * sWg[e] + sbr[e];
            mx = fmaxf(mx, acc[e]);
        }
        float s = 0.f;
#pragma unroll
        for (int e = 0; e < EEXP; e++) { acc[e] = expf(acc[e] - mx); s += acc[e]; }
        const float inv = 1.f / s;
#pragma unroll
        for (int e = 0; e < EEXP; e++) {
            acc[e] *= inv;
            probs_out[(size_t)n * EEXP + e] = acc[e];
        }
        int e0 = 0;
#pragma unroll
        for (int e = 1; e < EEXP; e++) if (acc[e] > acc[e0]) e0 = e;
        int e1 = (e0 == 0) ? 1 : 0;
#pragma unroll
        for (int e = 0; e < EEXP; e++) if (e != e0 && acc[e] > acc[e1]) e1 = e;

        int p0 = atomicAdd(&g_cnt[e0], 1);
        g_idx[e0 * NTOK + p0] = (n << 1);
        g_w  [e0 * NTOK + p0] = acc[e0];
        int p1 = atomicAdd(&g_cnt[e1], 1);
        g_idx[e1 * NTOK + p1] = (n << 1) | 1;
        g_w  [e1 * NTOK + p1] = acc[e1];
    }
}

// ---------------- launches 3/4: HMMA GEMM, 128x128 tile, K-chunk 64, 3-stage, 1 sync/chunk ----
// Stage (32KB): A[128][64] @0 | B[128][64] @16K  (fp16, 128B rows, SW128)
// G1=true : A = gathered x (K=256), B = W1T, epilogue gelu_fast -> g_hh
// G1=false: A = g_hh (K=1024), B = W2T, epilogue w*(acc+b2) half2-store -> g_yp
template<int KDIM, bool G1>
__global__ __launch_bounds__(256, 2)
void moe_gemm_kernel(const float* __restrict__ bias) {
    constexpr int NC = KDIM / 64;
    constexpr int BROWS = G1 ? HDIM : DDIM;
    constexpr uint32_t STAGE = 32768;

    const int e = blockIdx.z;
    int off = 0;
#pragma unroll
    for (int i = 0; i < EEXP; i++) if (i < e) off += g_cnt[i];
    const int cnt = g_cnt[e];
    const int m0 = blockIdx.y * 128;
    if (m0 >= cnt) return;
    const int n0 = blockIdx.x * 128;
    const int mRem = min(cnt - m0, 128);

    extern __shared__ char smem[];
    const uint32_t sb = smem_u32(smem);
    __shared__ float sBias[128];

    const int tid = threadIdx.x, lane = tid & 31, wid = tid >> 5;
    const int warpM = wid & 3, warpN = wid >> 2;   // 4x2 warps, warp tile 32x64

    if (tid < 128) sBias[tid] = bias[e * BROWS + n0 + tid];

    // loader: row lr = tid>>1, half lh = tid&1 (64B each, 4x16B)
    const int lr = tid >> 1, lh = tid & 1;
    const bool aval = lr < mRem;
    const __half* arow;
    {
        int row;
        if (G1) row = aval ? (g_idx[e * NTOK + m0 + lr] >> 1) : 0;
        else    row = aval ? (off + m0 + lr) : 0;
        arow = (G1 ? g_xh : g_hh) + (size_t)row * KDIM;
    }
    const __half* bt = (G1 ? g_w1t : g_w2t) + ((size_t)e * BROWS + n0 + lr) * KDIM;
    const int asz = aval ? 16 : 0;

    uint32_t stW[4];
#pragma unroll
    for (int j = 0; j < 4; j++) stW[j] = swz((uint32_t)lr * 128 + lh * 64 + j * 16);

    // ldmatrix UNSWIZZLED base offsets; swizzle applied at use: swz(base + ks*32)
    uint32_t aoff[2], boff[4];
#pragma unroll
    for (int mt = 0; mt < 2; mt++) {
        const uint32_t row = warpM * 32 + mt * 16 + (lane & 15);
        aoff[mt] = row * 128 + (lane >> 4) * 16;
    }
#pragma unroll
    for (int btj = 0; btj < 4; btj++) {
        const uint32_t row = warpN * 64 + btj * 16 + (lane & 7) + ((lane >> 4) & 1) * 8;
        boff[btj] = row * 128 + ((lane >> 3) & 1) * 16;
    }

    float acc[2][8][4];
#pragma unroll
    for (int i = 0; i < 2; i++)
#pragma unroll
        for (int j = 0; j < 8; j++)
#pragma unroll
            for (int q = 0; q < 4; q++) acc[i][j][q] = 0.f;

    auto load_chunk = [&](int kc, int stage) {
        const uint32_t s = sb + (uint32_t)stage * STAGE;
        const int go = kc * 64 + lh * 32;   // halves
#pragma unroll
        for (int j = 0; j < 4; j++) {
            cpa(s + stW[j],          arow + go + j * 8, asz);
            cpa(s + 16384u + stW[j], bt   + go + j * 8, 16);
        }
    };

    load_chunk(0, 0);
    cpa_commit();
    if (NC > 1) { load_chunk(1, 1); cpa_commit(); }

    int stage = 0;
    for (int c = 0; c < NC; c++) {
        if (c + 1 < NC) cpa_wait<1>(); else cpa_wait<0>();
        __syncthreads();
        if (c + 2 < NC) {
            int ps = stage + 2; if (ps >= 3) ps -= 3;
            load_chunk(c + 2, ps);
            cpa_commit();
        }

        const uint32_t ss = sb + (uint32_t)stage * STAGE;
#pragma unroll
        for (int ks = 0; ks < 4; ks++) {
            uint32_t ah[2][4], bb[4][4];
            ldsm4(ah[0], ss + swz(aoff[0] + ks * 32));
            ldsm4(ah[1], ss + swz(aoff[1] + ks * 32));
#pragma unroll
            for (int btj = 0; btj < 4; btj++)
                ldsm4(bb[btj], ss + 16384u + swz(boff[btj] + ks * 32));
#pragma unroll
            for (int mt = 0; mt < 2; mt++)
#pragma unroll
                for (int btj = 0; btj < 4; btj++) {
                    mma16816(acc[mt][2 * btj],     ah[mt], bb[btj][0], bb[btj][1]);
                    mma16816(acc[mt][2 * btj + 1], ah[mt], bb[btj][2], bb[btj][3]);
                }
        }
        if (++stage == 3) stage = 0;
    }

    // ---------------- epilogue ----------------
    const int gid = lane >> 2, tig = lane & 3;
#pragma unroll
    for (int mt = 0; mt < 2; mt++) {
#pragma unroll
        for (int half = 0; half < 2; half++) {
            const int ml = warpM * 32 + mt * 16 + gid + half * 8;
            if (ml >= mRem) continue;
            if (G1) {
                __half* hbase = g_hh + (size_t)(off + m0 + ml) * HDIM + n0 + warpN * 64 + tig * 2;
#pragma unroll
                for (int nt = 0; nt < 8; nt++) {
                    const int col = warpN * 64 + nt * 8 + tig * 2;
                    const float v0 = gelu_fast(acc[mt][nt][half * 2]     + sBias[col]);
                    const float v1 = gelu_fast(acc[mt][nt][half * 2 + 1] + sBias[col + 1]);
                    const __half2 hp = __floats2half2_rn(v0, v1);
                    *(__half2*)(hbase + nt * 8) = hp;
                }
            } else {
                const int ent = g_idx[e * NTOK + m0 + ml];
                const float wgt = g_w[e * NTOK + m0 + ml];
                __half* dst = g_yp + (size_t)ent * DDIM + n0 + warpN * 64 + tig * 2;
#pragma unroll
                for (int nt = 0; nt < 8; nt++) {
                    const int col = warpN * 64 + nt * 8 + tig * 2;
                    const float v0 = wgt * (acc[mt][nt][half * 2]     + sBias[col]);
                    const float v1 = wgt * (acc[mt][nt][half * 2 + 1] + sBias[col + 1]);
                    const __half2 hp = __floats2half2_rn(v0, v1);
                    *(__half2*)(dst + nt * 8) = hp;
                }
            }
        }
    }
}

// ---------------- launch 5: combine the two weighted slots per token (half2 in, fp32 out) ----
__global__ void combine_kernel(float* __restrict__ out) {
    const int i = blockIdx.x * blockDim.x + threadIdx.x;   // over N*D/4 float4s
    const int n  = i >> 6;          // DDIM/4 = 64 float4s per token
    const int d4 = i & 63;
    const __half2* yp2 = (const __half2*)g_yp;             // 128 half2 per row
    const size_t base = (size_t)n * 256 + d4 * 2;          // slot0 row
    const __half2 a0 = yp2[base],       a1 = yp2[base + 1];
    const __half2 b0 = yp2[base + 128], b1 = yp2[base + 129];
    const float2 fa0 = __half22float2(a0), fa1 = __half22float2(a1);
    const float2 fb0 = __half22float2(b0), fb1 = __half22float2(b1);
    float4 r;
    r.x = fa0.x + fb0.x; r.y = fa0.y + fb0.y;
    r.z = fa1.x + fb1.x; r.w = fa1.y + fb1.y;
    ((float4*)out)[i] = r;
}

// ---------------- launch ----------------
extern "C" void kernel_launch(void* const* d_in, const int* in_sizes, int n_in,
                              void* d_out, int out_size) {
    const float* x    = (const float*)d_in[0];
    const float* grad = (const float*)d_in[1];
    const float* Wr   = (const float*)d_in[2];
    const float* br   = (const float*)d_in[3];
    const float* W1   = (const float*)d_in[4];
    const float* b1   = (const float*)d_in[5];
    const float* W2   = (const float*)d_in[6];
    const float* b2   = (const float*)d_in[7];
    float* out   = (float*)d_out;
    float* probs = out + (size_t)NTOK * DDIM;

    const int SMEM_DYN = 3 * 32768;
    cudaFuncSetAttribute(moe_gemm_kernel<DDIM, true>,  cudaFuncAttributeMaxDynamicSharedMemorySize, SMEM_DYN);
    cudaFuncSetAttribute(moe_gemm_kernel<HDIM, false>, cudaFuncAttributeMaxDynamicSharedMemorySize, SMEM_DYN);

    prep_w_kernel<<<dim3(32, 8, 16), dim3(32, 32)>>>(W1, W2);                     // 1 (+cnt reset)
    router_kernel<<<NTOK / 8, 256>>>(x, grad, Wr, br, probs);                     // 2
    moe_gemm_kernel<DDIM, true><<<dim3(HDIM / 128, NTOK / 128, EEXP), 256, SMEM_DYN>>>(b1);  // 3
    moe_gemm_kernel<HDIM, false><<<dim3(DDIM / 128, NTOK / 128, EEXP), 256, SMEM_DYN>>>(b2); // 4 (profiled)
    combine_kernel<<<(NTOK * DDIM / 4) / 256, 256>>>(out);                        // 5
}